// round 3
// baseline (speedup 1.0000x reference)
#include <cuda_runtime.h>

#define NUM_G 4096
#define D4    32          // 128 floats = 32 float4 per row
#define TPB   256
#define RG    8           // row groups in pass 1 (TPB / 32)
#define EPSV  1e-5f

__device__ int g_seg_off[NUM_G + 1];

// One thread per graph boundary: binary search lower_bound(g) over sorted batch.
// Runtime dtype detection: if batch is int64 (LE), odd 32-bit words near the end
// are high words of values < 4096 -> all zero. If int32, the tail values ~4095.
__global__ void offsets_kernel(const int* __restrict__ b32, int n)
{
    int g = blockIdx.x * blockDim.x + threadIdx.x;
    if (g > NUM_G) return;
    int probe = b32[n - 1] | b32[n - 3] | b32[n - 5] | b32[n - 7];
    int sh = (probe == 0) ? 1 : 0;   // 1 => int64, read low words at stride 2
    int lo = 0, hi = n;
    while (lo < hi) {
        int mid = (lo + hi) >> 1;
        int v = b32[(long long)mid << sh];
        if (v < g) lo = mid + 1; else hi = mid;
    }
    g_seg_off[g] = lo;
}

__device__ __forceinline__ void acc(float4& s, float4& q, const float4 v)
{
    s.x += v.x; s.y += v.y; s.z += v.z; s.w += v.w;
    q.x += v.x * v.x; q.y += v.y * v.y;
    q.z += v.z * v.z; q.w += v.w * v.w;
}

__global__ __launch_bounds__(TPB) void graphnorm_kernel(
    const float4* __restrict__ x4,
    const float*  __restrict__ weight,
    const float*  __restrict__ bias,
    float4*       __restrict__ out4)
{
    __shared__ float4 red_s[RG][D4];
    __shared__ float4 red_q[RG][D4];
    __shared__ float4 sc_s[D4];
    __shared__ float4 sh_s[D4];

    const int g   = blockIdx.x;
    const int tid = threadIdx.x;
    const int c4  = tid & (D4 - 1);   // float4 column
    const int rg  = tid >> 5;         // row group 0..RG-1

    const int start = g_seg_off[g];
    const int end   = g_seg_off[g + 1];
    const int cnt   = end - start;

    // ---- Pass 1: per-column sum / sumsq (unroll x4 for MLP) ----
    float4 s = make_float4(0.f, 0.f, 0.f, 0.f);
    float4 q = make_float4(0.f, 0.f, 0.f, 0.f);
    int r = start + rg;
    for (; r + 3 * RG < end; r += 4 * RG) {
        float4 v0 = x4[(r         ) * D4 + c4];
        float4 v1 = x4[(r +     RG) * D4 + c4];
        float4 v2 = x4[(r + 2 * RG) * D4 + c4];
        float4 v3 = x4[(r + 3 * RG) * D4 + c4];
        acc(s, q, v0);
        acc(s, q, v1);
        acc(s, q, v2);
        acc(s, q, v3);
    }
    for (; r < end; r += RG) {
        float4 v = x4[r * D4 + c4];
        acc(s, q, v);
    }
    red_s[rg][c4] = s;
    red_q[rg][c4] = q;
    __syncthreads();

    #pragma unroll
    for (int h = RG / 2; h >= 1; h >>= 1) {
        if (rg < h) {
            float4 a = red_s[rg][c4], b = red_s[rg + h][c4];
            a.x += b.x; a.y += b.y; a.z += b.z; a.w += b.w;
            red_s[rg][c4] = a;
            float4 c = red_q[rg][c4], d = red_q[rg + h][c4];
            c.x += d.x; c.y += d.y; c.z += d.z; c.w += d.w;
            red_q[rg][c4] = c;
        }
        __syncthreads();
    }

    // ---- Fold into scale/shift (warp 0) ----
    if (rg == 0) {
        float4 w = reinterpret_cast<const float4*>(weight)[c4];
        float4 b = reinterpret_cast<const float4*>(bias)[c4];
        float4 sc, sh;
        if (cnt > 1) {
            float4 S = red_s[0][c4];
            float4 Q = red_q[0][c4];
            float inv_n = 1.0f / (float)cnt;
            float mx = S.x * inv_n, my = S.y * inv_n, mz = S.z * inv_n, mw = S.w * inv_n;
            float vx = Q.x * inv_n - mx * mx;
            float vy = Q.y * inv_n - my * my;
            float vz = Q.z * inv_n - mz * mz;
            float vw = Q.w * inv_n - mw * mw;
            sc.x = w.x * rsqrtf(vx + EPSV);
            sc.y = w.y * rsqrtf(vy + EPSV);
            sc.z = w.z * rsqrtf(vz + EPSV);
            sc.w = w.w * rsqrtf(vw + EPSV);
            sh.x = b.x - mx * sc.x;
            sh.y = b.y - my * sc.y;
            sh.z = b.z - mz * sc.z;
            sh.w = b.w - mw * sc.w;
        } else {
            // cnt <= 1: reference leaves mean=0, var=1
            float rr = rsqrtf(1.0f + EPSV);
            sc.x = w.x * rr; sc.y = w.y * rr; sc.z = w.z * rr; sc.w = w.w * rr;
            sh = b;
        }
        sc_s[c4] = sc;
        sh_s[c4] = sh;
    }
    __syncthreads();

    // ---- Pass 2: normalize (unroll x4). Column index j & 31 is
    //      loop-invariant (TPB multiple of 32) -> hoist sc/sh. x re-read
    //      with evict-first; streaming stores for the output. ----
    const float4 sc = sc_s[c4];
    const float4 sh = sh_s[c4];
    const int jend = end * D4;
    int j = start * D4 + tid;
    for (; j + 3 * TPB < jend; j += 4 * TPB) {
        float4 v0 = __ldcs(&x4[j          ]);
        float4 v1 = __ldcs(&x4[j +     TPB]);
        float4 v2 = __ldcs(&x4[j + 2 * TPB]);
        float4 v3 = __ldcs(&x4[j + 3 * TPB]);
        float4 o0, o1, o2, o3;
        o0.x = v0.x * sc.x + sh.x; o0.y = v0.y * sc.y + sh.y;
        o0.z = v0.z * sc.z + sh.z; o0.w = v0.w * sc.w + sh.w;
        o1.x = v1.x * sc.x + sh.x; o1.y = v1.y * sc.y + sh.y;
        o1.z = v1.z * sc.z + sh.z; o1.w = v1.w * sc.w + sh.w;
        o2.x = v2.x * sc.x + sh.x; o2.y = v2.y * sc.y + sh.y;
        o2.z = v2.z * sc.z + sh.z; o2.w = v2.w * sc.w + sh.w;
        o3.x = v3.x * sc.x + sh.x; o3.y = v3.y * sc.y + sh.y;
        o3.z = v3.z * sc.z + sh.z; o3.w = v3.w * sc.w + sh.w;
        __stcs(&out4[j          ], o0);
        __stcs(&out4[j +     TPB], o1);
        __stcs(&out4[j + 2 * TPB], o2);
        __stcs(&out4[j + 3 * TPB], o3);
    }
    for (; j < jend; j += TPB) {
        float4 v = __ldcs(&x4[j]);
        float4 o;
        o.x = v.x * sc.x + sh.x;
        o.y = v.y * sc.y + sh.y;
        o.z = v.z * sc.z + sh.z;
        o.w = v.w * sc.w + sh.w;
        __stcs(&out4[j], o);
    }
}

extern "C" void kernel_launch(void* const* d_in, const int* in_sizes, int n_in,
                              void* d_out, int out_size)
{
    const float* x      = (const float*)d_in[0];
    const int*   batch  = (const int*)d_in[1];   // int32 or int64; detected on device
    const float* weight = (const float*)d_in[2];
    const float* bias   = (const float*)d_in[3];
    float*       out    = (float*)d_out;

    int n = in_sizes[1];  // number of nodes

    offsets_kernel<<<(NUM_G + 1 + 255) / 256, 256>>>(batch, n);
    graphnorm_kernel<<<NUM_G, TPB>>>(
        reinterpret_cast<const float4*>(x), weight, bias,
        reinterpret_cast<float4*>(out));
}